// round 3
// baseline (speedup 1.0000x reference)
#include <cuda_runtime.h>
#include <cuda_bf16.h>
#include <math.h>
#include <stdint.h>

#define NB 64
#define NS 256
#define NE 300
#define NH 300
#define NH2 600
#define NH4 1200
#define NR 512
#define NRELN 46
#define NRELD 50
#define NV 30000

// ------------------------- static scratch (no allocation) -------------------------
__device__ float g_text[(size_t)NB * NS * NE];          // [B*S, 300]
__device__ float g_Xf[(size_t)NB * NS * NH4];           // [B*S, 1200]
__device__ float g_Xb[(size_t)NB * NS * NH4];
__device__ float g_WihTf[NE * NH4];                     // [300][1200]
__device__ float g_WihTb[NE * NH4];
__device__ float g_WhhTf[NH * NH4];                     // [300][1200]
__device__ float g_WhhTb[NH * NH4];
__device__ float g_h[2 * 2 * NB * NH];                  // [dir][parity][b][u]
__device__ float g_c[2 * NB * NH];                      // [dir][b][u]
__device__ float g_to[(size_t)NB * NS * NH2];           // text_out [B,S,600]
__device__ float g_adj[(size_t)NB * NS * NS];           // modified adj
__device__ float g_denom[NB * NS];
__device__ float g_P[NRELN * NH4];                      // bil_W @ rel_embed[r]
__device__ int   g_len[3 * NB];                         // left, aspect, text
__device__ float g_pw[(size_t)NB * NS * NH2];
__device__ float g_H[(size_t)NB * NS * NH2];
__device__ float g_A[(size_t)NB * NS * NH2];
__device__ float g_X1[(size_t)NB * NS * NH2];
__device__ float g_v[NB * NH2];

// ------------------------- small helpers -------------------------
__device__ __forceinline__ float sigmoidf_(float x) { return 1.0f / (1.0f + expf(-x)); }

// ------------------------- lengths -------------------------
__global__ void k_lens(const int* __restrict__ ti, const int* __restrict__ ai,
                       const int* __restrict__ li) {
    int b = threadIdx.x;
    if (b >= NB) return;
    int ll = 0;
    for (int s = 0; s < 64; s++) ll += (li[b * 64 + s] != 0);
    int al = 0;
    for (int s = 0; s < 4; s++) al += (ai[b * 4 + s] != 0);
    int tl = 0;
    for (int s = 0; s < NS; s++) tl += (ti[b * NS + s] != 0);
    g_len[b] = ll;
    g_len[NB + b] = al;
    g_len[2 * NB + b] = tl;
}

// ------------------------- embedding gather -------------------------
__global__ void k_embed(const int* __restrict__ idx, const float* __restrict__ tab) {
    size_t i = (size_t)blockIdx.x * blockDim.x + threadIdx.x;
    size_t n = (size_t)NB * NS * NE;
    if (i >= n) return;
    int row = (int)(i / NE);
    int e = (int)(i % NE);
    g_text[i] = tab[(size_t)idx[row] * NE + e];
}

// ------------------------- transpose [R,C] -> [C,R] -------------------------
__global__ void k_transpose(const float* __restrict__ src, float* __restrict__ dst,
                            int R, int C) {
    int i = blockIdx.x * blockDim.x + threadIdx.x;
    if (i >= R * C) return;
    int r = i / C, c = i % C;
    dst[c * R + r] = src[i];
}

// ------------------------- P[rel] = bil_W @ rel_embed[rel] -------------------------
__global__ void k_pcomp(const float* __restrict__ bilW, const float* __restrict__ relE) {
    int rel = blockIdx.x;
    for (int u = threadIdx.x; u < NH4; u += blockDim.x) {
        float a = 0.f;
        for (int d = 0; d < NRELD; d++) a += bilW[u * NRELD + d] * relE[rel * NRELD + d];
        g_P[rel * NH4 + u] = a;
    }
}

// ------------------------- zero LSTM state -------------------------
__global__ void k_zero_state() {
    int n1 = 2 * 2 * NB * NH, n2 = 2 * NB * NH;
    for (int i = blockIdx.x * blockDim.x + threadIdx.x; i < n1 + n2;
         i += gridDim.x * blockDim.x) {
        if (i < n1) g_h[i] = 0.f; else g_c[i - n1] = 0.f;
    }
}

// ------------------------- generic fp32 GEMM: C = A[M,K] x B[K,N] (+bias) -------------------------
#define BM 128
#define BN 64
#define BKK 16
__global__ void __launch_bounds__(256) gemm_nn(
    const float* __restrict__ A, const float* __restrict__ B, float* __restrict__ C,
    const float* __restrict__ bias, int M, int N, int K, long sA, long sB, long sC) {
    A += (size_t)blockIdx.z * sA;
    B += (size_t)blockIdx.z * sB;
    C += (size_t)blockIdx.z * sC;
    int m0 = blockIdx.y * BM, n0 = blockIdx.x * BN;
    __shared__ float As[BKK][BM + 4];
    __shared__ float Bs[BKK][BN];
    int tid = threadIdx.x;
    int tx = tid & 15, ty = tid >> 4;
    float acc[8][4];
#pragma unroll
    for (int i = 0; i < 8; i++)
#pragma unroll
        for (int j = 0; j < 4; j++) acc[i][j] = 0.f;

    for (int k0 = 0; k0 < K; k0 += BKK) {
#pragma unroll
        for (int i = 0; i < 8; i++) {
            int l = tid + i * 256;             // 0..2047
            int r = l >> 4, kk = l & 15;
            int gm = m0 + r, gk = k0 + kk;
            As[kk][r] = (gm < M && gk < K) ? A[(size_t)gm * K + gk] : 0.f;
        }
#pragma unroll
        for (int i = 0; i < 4; i++) {
            int l = tid + i * 256;             // 0..1023
            int kk = l >> 6, n = l & 63;
            int gk = k0 + kk, gn = n0 + n;
            Bs[kk][n] = (gk < K && gn < N) ? B[(size_t)gk * N + gn] : 0.f;
        }
        __syncthreads();
#pragma unroll
        for (int kk = 0; kk < BKK; kk++) {
            float ar[8], br[4];
#pragma unroll
            for (int i = 0; i < 8; i++) ar[i] = As[kk][ty * 8 + i];
#pragma unroll
            for (int j = 0; j < 4; j++) br[j] = Bs[kk][tx * 4 + j];
#pragma unroll
            for (int i = 0; i < 8; i++)
#pragma unroll
                for (int j = 0; j < 4; j++) acc[i][j] += ar[i] * br[j];
        }
        __syncthreads();
    }
#pragma unroll
    for (int i = 0; i < 8; i++) {
        int gm = m0 + ty * 8 + i;
        if (gm >= M) continue;
#pragma unroll
        for (int j = 0; j < 4; j++) {
            int gn = n0 + tx * 4 + j;
            if (gn >= N) continue;
            float vv = acc[i][j];
            if (bias) vv += bias[gn];
            C[(size_t)gm * N + gn] = vv;
        }
    }
}

// ------------------------- LSTM step -------------------------
// grid (3 utiles x 16 bgroups x 2 dirs), 128 threads; thread = unit (tid<100), 4 batches, 4 gates
__global__ void __launch_bounds__(128) lstm_step(int t) {
    int utile = blockIdx.x, bg = blockIdx.y, dir = blockIdx.z;
    int tid = threadIdx.x;
    int p = t & 1;
    __shared__ float hs[4][NH];
    int b0 = bg * 4;
    const float* hold = &g_h[((size_t)(dir * 2 + p) * NB) * NH];
    for (int i = tid; i < 4 * NH; i += 128) {
        int j = i / NH, k = i % NH;
        hs[j][k] = hold[(size_t)(b0 + j) * NH + k];
    }
    __syncthreads();
    if (tid >= 100) return;
    int u = utile * 100 + tid;
    const float* WT = dir ? g_WhhTb : g_WhhTf;
    float a0[4] = {0, 0, 0, 0}, a1[4] = {0, 0, 0, 0}, a2[4] = {0, 0, 0, 0}, a3[4] = {0, 0, 0, 0};
    for (int k = 0; k < NH; k++) {
        const float* wr = &WT[(size_t)k * NH4 + u];
        float w0 = wr[0], w1 = wr[300], w2 = wr[600], w3 = wr[900];
#pragma unroll
        for (int j = 0; j < 4; j++) {
            float h = hs[j][k];
            a0[j] += w0 * h;
            a1[j] += w1 * h;
            a2[j] += w2 * h;
            a3[j] += w3 * h;
        }
    }
    int t_eff = dir ? (NS - 1 - t) : t;
    const float* X = dir ? g_Xb : g_Xf;
#pragma unroll
    for (int j = 0; j < 4; j++) {
        int b = b0 + j;
        const float* xr = &X[((size_t)b * NS + t_eff) * NH4];
        float gi = a0[j] + xr[u];
        float gf = a1[j] + xr[300 + u];
        float gg = a2[j] + xr[600 + u];
        float go = a3[j] + xr[900 + u];
        float ii = sigmoidf_(gi), ff = sigmoidf_(gf), oo = sigmoidf_(go);
        float gt = tanhf(gg);
        size_t cidx = ((size_t)dir * NB + b) * NH + u;
        float c = ff * g_c[cidx] + ii * gt;
        g_c[cidx] = c;
        float h = oo * tanhf(c);
        g_h[((size_t)(dir * 2 + (1 - p)) * NB + b) * NH + u] = h;
        g_to[((size_t)b * NS + t_eff) * NH2 + dir * NH + u] = h;
    }
}

// ------------------------- adj copy -------------------------
__global__ void k_adjcopy(const float* __restrict__ adj) {
    size_t n = (size_t)NB * NS * NS;
    for (size_t i = (size_t)blockIdx.x * blockDim.x + threadIdx.x; i < n;
         i += (size_t)gridDim.x * blockDim.x)
        g_adj[i] = adj[i];
}

// ------------------------- relation bilinear score + scatter -------------------------
__global__ void k_score(const int* __restrict__ relv, const int* __restrict__ headv,
                        const int* __restrict__ beheadv, const float* __restrict__ bilb) {
    int warp = threadIdx.x >> 5, lane = threadIdx.x & 31;
    int idx = blockIdx.x * 8 + warp;                 // (b, r)
    if (idx >= NB * NR) return;
    int b = idx / NR, r = idx % NR;
    int rel = relv[b * NR + r];
    int hd = headv[b * NR + r];
    int bh = beheadv[b * NR + r];
    float s = 0.f;
    if (rel != 0) {
        const float* n1 = &g_to[((size_t)b * NS + hd) * NH2];
        const float* n2 = &g_to[((size_t)b * NS + bh) * NH2];
        const float* Pp = &g_P[(size_t)rel * NH4];
        for (int u = lane; u < NH2; u += 32) s += n1[u] * Pp[u] + n2[u] * Pp[NH2 + u];
    }
#pragma unroll
    for (int o = 16; o; o >>= 1) s += __shfl_xor_sync(0xffffffffu, s, o);
    if (lane == 0) {
        float sc = 1.0f / (1.0f + expf(-(s + bilb[0])));
        g_adj[((size_t)b * NS + hd) * NS + bh] = sc;
    }
}

// ------------------------- row-sum denom -------------------------
__global__ void k_denom() {
    int warp = threadIdx.x >> 5, lane = threadIdx.x & 31;
    int row = blockIdx.x * 8 + warp;                 // (b, s)
    if (row >= NB * NS) return;
    const float* ar = &g_adj[(size_t)row * NS];
    float s = 0.f;
    for (int c = lane; c < NS; c += 32) s += ar[c];
#pragma unroll
    for (int o = 16; o; o >>= 1) s += __shfl_xor_sync(0xffffffffu, s, o);
    if (lane == 0) g_denom[row] = s + 1.0f;
}

// ------------------------- position weight -------------------------
__global__ void k_poswt(const float* __restrict__ in, float* __restrict__ out) {
    size_t n = (size_t)NB * NS * NH2;
    for (size_t i = (size_t)blockIdx.x * blockDim.x + threadIdx.x; i < n;
         i += (size_t)gridDim.x * blockDim.x) {
        int bs = (int)(i / NH2);
        int b = bs / NS, j = bs % NS;
        float l0 = (float)g_len[b];
        float al = (float)g_len[NB + b];
        float tl = (float)g_len[2 * NB + b];
        float l1 = l0 + al - 1.0f;
        float ctx = tl - al;
        float jj = (float)j;
        float w;
        if (jj < l0) w = 1.0f - (l0 - jj) / ctx;
        else if (jj <= l1) w = 0.0f;
        else if (jj < tl) w = 1.0f - (jj - l1) / ctx;
        else w = 0.0f;
        out[i] = w * in[i];
    }
}

// ------------------------- relu(A/denom + bias) -------------------------
__global__ void k_reludb(const float* __restrict__ in, float* __restrict__ out,
                         const float* __restrict__ bias) {
    size_t n = (size_t)NB * NS * NH2;
    for (size_t i = (size_t)blockIdx.x * blockDim.x + threadIdx.x; i < n;
         i += (size_t)gridDim.x * blockDim.x) {
        int bs = (int)(i / NH2);
        int u = (int)(i % NH2);
        float x = in[i] / g_denom[bs] + bias[u];
        out[i] = x > 0.f ? x : 0.f;
    }
}

// ------------------------- masked column sum v[b] = sum_{j in [l0,l1]} X2[b,j,:] ------------
__global__ void k_vmask() {
    int b = blockIdx.x;
    int l0 = g_len[b];
    int l1 = l0 + g_len[NB + b] - 1;
    if (l1 > NS - 1) l1 = NS - 1;
    for (int u = threadIdx.x; u < NH2; u += blockDim.x) {
        float a = 0.f;
        for (int j = l0; j <= l1; j++) a += g_A[((size_t)b * NS + j) * NH2 + u];
        g_v[b * NH2 + u] = a;
    }
}

// ------------------------- attention + fc -------------------------
__global__ void __launch_bounds__(256) k_attend(const float* __restrict__ fcW,
                                                const float* __restrict__ fcb,
                                                float* __restrict__ out) {
    int b = blockIdx.x;
    __shared__ float lg[NS];
    __shared__ float red[8];
    __shared__ float ov[NH2];
    int tid = threadIdx.x, warp = tid >> 5, lane = tid & 31;
    // logits[s] = v[b] . text_out[b,s,:]
    for (int s = warp; s < NS; s += 8) {
        const float* tr = &g_to[((size_t)b * NS + s) * NH2];
        float a = 0.f;
        for (int u = lane; u < NH2; u += 32) a += g_v[b * NH2 + u] * tr[u];
#pragma unroll
        for (int o = 16; o; o >>= 1) a += __shfl_xor_sync(0xffffffffu, a, o);
        if (lane == 0) lg[s] = a;
    }
    __syncthreads();
    // softmax over 256
    float v = lg[tid];
    float m = v;
#pragma unroll
    for (int o = 16; o; o >>= 1) m = fmaxf(m, __shfl_xor_sync(0xffffffffu, m, o));
    if (lane == 0) red[warp] = m;
    __syncthreads();
    if (tid == 0) {
        float mm = red[0];
        for (int w = 1; w < 8; w++) mm = fmaxf(mm, red[w]);
        red[0] = mm;
    }
    __syncthreads();
    float mx = red[0];
    float e = expf(v - mx);
    float s = e;
#pragma unroll
    for (int o = 16; o; o >>= 1) s += __shfl_xor_sync(0xffffffffu, s, o);
    __syncthreads();
    if (lane == 0) red[warp] = s;
    __syncthreads();
    if (tid == 0) {
        float ss = 0.f;
        for (int w = 0; w < 8; w++) ss += red[w];
        red[0] = ss;
    }
    __syncthreads();
    float alpha = e / red[0];
    lg[tid] = alpha;
    __syncthreads();
    // ov[u] = sum_s alpha[s]*text_out[b,s,u]
    for (int u = tid; u < NH2; u += 256) {
        float a = 0.f;
        for (int ss = 0; ss < NS; ss++) a += lg[ss] * g_to[((size_t)b * NS + ss) * NH2 + u];
        ov[u] = a;
    }
    __syncthreads();
    if (tid < 3) {
        float a = fcb[tid];
        for (int u = 0; u < NH2; u++) a += ov[u] * fcW[u * 3 + tid];
        out[b * 3 + tid] = a;
    }
}

// ------------------------- launch -------------------------
extern "C" void kernel_launch(void* const* d_in, const int* in_sizes, int n_in,
                              void* d_out, int out_size) {
    const int* ti = (const int*)d_in[0];
    const int* ai = (const int*)d_in[1];
    const int* li = (const int*)d_in[2];
    const float* adj = (const float*)d_in[3];
    const int* headv = (const int*)d_in[4];
    const int* beheadv = (const int*)d_in[5];
    const int* relv = (const int*)d_in[6];
    const float* emb = (const float*)d_in[7];
    const float* relE = (const float*)d_in[8];
    const float* Wf_ih = (const float*)d_in[9];
    const float* Wf_hh = (const float*)d_in[10];
    const float* bf = (const float*)d_in[11];
    const float* Wb_ih = (const float*)d_in[12];
    const float* Wb_hh = (const float*)d_in[13];
    const float* bb = (const float*)d_in[14];
    const float* bilW = (const float*)d_in[15];
    const float* bilb = (const float*)d_in[16];
    const float* gc1W = (const float*)d_in[17];
    const float* gc1b = (const float*)d_in[18];
    const float* gc2W = (const float*)d_in[19];
    const float* gc2b = (const float*)d_in[20];
    const float* fcW = (const float*)d_in[21];
    const float* fcb = (const float*)d_in[22];
    float* out = (float*)d_out;

    k_lens<<<1, 64>>>(ti, ai, li);

    {
        size_t n = (size_t)NB * NS * NE;
        k_embed<<<(int)((n + 255) / 256), 256>>>(ti, emb);
    }

    int tblk = (NH4 * NE + 255) / 256;
    float* WihTf; cudaGetSymbolAddress((void**)&WihTf, g_WihTf);
    float* WihTb; cudaGetSymbolAddress((void**)&WihTb, g_WihTb);
    float* WhhTf; cudaGetSymbolAddress((void**)&WhhTf, g_WhhTf);
    float* WhhTb; cudaGetSymbolAddress((void**)&WhhTb, g_WhhTb);
    float* textp; cudaGetSymbolAddress((void**)&textp, g_text);
    float* Xfp;   cudaGetSymbolAddress((void**)&Xfp, g_Xf);
    float* Xbp;   cudaGetSymbolAddress((void**)&Xbp, g_Xb);
    float* top;   cudaGetSymbolAddress((void**)&top, g_to);
    float* adjp;  cudaGetSymbolAddress((void**)&adjp, g_adj);
    float* pwp;   cudaGetSymbolAddress((void**)&pwp, g_pw);
    float* Hp;    cudaGetSymbolAddress((void**)&Hp, g_H);
    float* Ap;    cudaGetSymbolAddress((void**)&Ap, g_A);
    float* X1p;   cudaGetSymbolAddress((void**)&X1p, g_X1);

    k_transpose<<<tblk, 256>>>(Wf_ih, WihTf, NH4, NE);
    k_transpose<<<tblk, 256>>>(Wb_ih, WihTb, NH4, NE);
    k_transpose<<<tblk, 256>>>(Wf_hh, WhhTf, NH4, NH);
    k_transpose<<<tblk, 256>>>(Wb_hh, WhhTb, NH4, NH);

    k_pcomp<<<NRELN, 256>>>(bilW, relE);

    // input projections (+bias)
    {
        dim3 g((NH4 + BN - 1) / BN, (NB * NS + BM - 1) / BM, 1);
        gemm_nn<<<g, 256>>>(textp, WihTf, Xfp, bf, NB * NS, NH4, NE, 0, 0, 0);
        gemm_nn<<<g, 256>>>(textp, WihTb, Xbp, bb, NB * NS, NH4, NE, 0, 0, 0);
    }

    k_zero_state<<<256, 256>>>();
    for (int t = 0; t < NS; t++) lstm_step<<<dim3(3, 16, 2), 128>>>(t);

    {
        size_t n = (size_t)NB * NS * NS;
        k_adjcopy<<<2048, 256>>>(adj);
        (void)n;
    }
    k_score<<<(NB * NR + 7) / 8, 256>>>(relv, headv, beheadv, bilb);
    k_denom<<<(NB * NS + 7) / 8, 256>>>();

    // GCN layer 1
    k_poswt<<<4096, 256>>>(top, pwp);
    {
        dim3 g((NH2 + BN - 1) / BN, (NB * NS + BM - 1) / BM, 1);
        gemm_nn<<<g, 256>>>(pwp, gc1W, Hp, nullptr, NB * NS, NH2, NH2, 0, 0, 0);
    }
    {
        dim3 g((NH2 + BN - 1) / BN, (NS + BM - 1) / BM, NB);
        gemm_nn<<<g, 256>>>(adjp, Hp, Ap, nullptr, NS, NH2, NS,
                            (long)NS * NS, (long)NS * NH2, (long)NS * NH2);
    }
    k_reludb<<<4096, 256>>>(Ap, X1p, gc1b);

    // GCN layer 2
    k_poswt<<<4096, 256>>>(X1p, pwp);
    {
        dim3 g((NH2 + BN - 1) / BN, (NB * NS + BM - 1) / BM, 1);
        gemm_nn<<<g, 256>>>(pwp, gc2W, Hp, nullptr, NB * NS, NH2, NH2, 0, 0, 0);
    }
    {
        dim3 g((NH2 + BN - 1) / BN, (NS + BM - 1) / BM, NB);
        gemm_nn<<<g, 256>>>(adjp, Hp, Ap, nullptr, NS, NH2, NS,
                            (long)NS * NS, (long)NS * NH2, (long)NS * NH2);
    }
    k_reludb<<<4096, 256>>>(Ap, Ap, gc2b);

    // mask-sum, attention, fc
    k_vmask<<<NB, 256>>>();
    k_attend<<<NB, 256>>>(fcW, fcb, out);
}

// round 14
// speedup vs baseline: 1.0074x; 1.0074x over previous
#include <cuda_runtime.h>
#include <cuda_bf16.h>
#include <math.h>
#include <stdint.h>

#define NB 64
#define NS 256
#define NE 300
#define NH 300
#define NH2 600
#define NH4 1200
#define NR 512
#define NRELN 46
#define NRELD 50
#define NV 30000

// ------------------------- static scratch (no allocation) -------------------------
__device__ float g_text[(size_t)NB * NS * NE];          // [B*S, 300]
__device__ float g_Xf[(size_t)NB * NS * NH4];           // [B*S, 1200]
__device__ float g_Xb[(size_t)NB * NS * NH4];
__device__ float g_WihTf[NE * NH4];                     // [300][1200]
__device__ float g_WihTb[NE * NH4];
__device__ float g_WhhTf[NH * NH4];                     // [300][1200]
__device__ float g_WhhTb[NH * NH4];
__device__ float g_h[2 * 2 * NB * NH];                  // [dir][parity][b][u]
__device__ float g_c[2 * NB * NH];                      // [dir][b][u]
__device__ float g_to[(size_t)NB * NS * NH2];           // text_out [B,S,600]
__device__ float g_adj[(size_t)NB * NS * NS];           // modified adj
__device__ float g_denom[NB * NS];
__device__ float g_P[NRELN * NH4];                      // bil_W @ rel_embed[r]
__device__ int   g_len[3 * NB];                         // left, aspect, text
__device__ float g_pw[(size_t)NB * NS * NH2];
__device__ float g_H[(size_t)NB * NS * NH2];
__device__ float g_A[(size_t)NB * NS * NH2];
__device__ float g_X1[(size_t)NB * NS * NH2];
__device__ float g_v[NB * NH2];

// ------------------------- small helpers -------------------------
__device__ __forceinline__ float sigmoidf_(float x) { return 1.0f / (1.0f + expf(-x)); }
// fast variants for the LSTM hot loop: MUFU ex2-based, rel err ~1e-6
__device__ __forceinline__ float fsigmoid_(float x) {
    return __fdividef(1.0f, 1.0f + __expf(-x));
}
__device__ __forceinline__ float ftanh_(float x) {
    // 1 - 2/(e^{2x}+1); saturates correctly: x->+inf => 1, x->-inf => -1
    return 1.0f - __fdividef(2.0f, __expf(2.0f * x) + 1.0f);
}

// ------------------------- lengths -------------------------
__global__ void k_lens(const int* __restrict__ ti, const int* __restrict__ ai,
                       const int* __restrict__ li) {
    int b = threadIdx.x;
    if (b >= NB) return;
    int ll = 0;
    for (int s = 0; s < 64; s++) ll += (li[b * 64 + s] != 0);
    int al = 0;
    for (int s = 0; s < 4; s++) al += (ai[b * 4 + s] != 0);
    int tl = 0;
    for (int s = 0; s < NS; s++) tl += (ti[b * NS + s] != 0);
    g_len[b] = ll;
    g_len[NB + b] = al;
    g_len[2 * NB + b] = tl;
}

// ------------------------- embedding gather (float4: 75 float4 per 300-elem row) ----------
__global__ void k_embed(const int* __restrict__ idx, const float* __restrict__ tab) {
    size_t i = (size_t)blockIdx.x * blockDim.x + threadIdx.x;
    size_t n = (size_t)NB * NS * (NE / 4);
    if (i >= n) return;
    int row = (int)(i / (NE / 4));
    int e4 = (int)(i % (NE / 4));
    const float4* src = (const float4*)(tab + (size_t)idx[row] * NE);
    float4* dst = (float4*)(g_text + (size_t)row * NE);
    dst[e4] = src[e4];
}

// ------------------------- transpose [R,C] -> [C,R] -------------------------
__global__ void k_transpose(const float* __restrict__ src, float* __restrict__ dst,
                            int R, int C) {
    int i = blockIdx.x * blockDim.x + threadIdx.x;
    if (i >= R * C) return;
    int r = i / C, c = i % C;
    dst[c * R + r] = src[i];
}

// ------------------------- P[rel] = bil_W @ rel_embed[rel] -------------------------
__global__ void k_pcomp(const float* __restrict__ bilW, const float* __restrict__ relE) {
    int rel = blockIdx.x;
    for (int u = threadIdx.x; u < NH4; u += blockDim.x) {
        float a = 0.f;
        for (int d = 0; d < NRELD; d++) a += bilW[u * NRELD + d] * relE[rel * NRELD + d];
        g_P[rel * NH4 + u] = a;
    }
}

// ------------------------- zero LSTM state -------------------------
__global__ void k_zero_state() {
    int n1 = 2 * 2 * NB * NH, n2 = 2 * NB * NH;
    for (int i = blockIdx.x * blockDim.x + threadIdx.x; i < n1 + n2;
         i += gridDim.x * blockDim.x) {
        if (i < n1) g_h[i] = 0.f; else g_c[i - n1] = 0.f;
    }
}

// ------------------------- fp32 GEMM: C = A[M,K] x B[K,N] (+bias) -------------------------
// 128x128 tile, BK=16, quadrant 8x8 microtile, float4 smem reads,
// register-prefetch double buffering of the next K-slice over the compute phase.
#define BM 128
#define BN 128
#define BKK 16
__global__ void __launch_bounds__(256, 2) gemm_nn(
    const float* __restrict__ A, const float* __restrict__ B, float* __restrict__ C,
    const float* __restrict__ bias, int M, int N, int K, long sA, long sB, long sC) {
    A += (size_t)blockIdx.z * sA;
    B += (size_t)blockIdx.z * sB;
    C += (size_t)blockIdx.z * sC;
    int m0 = blockIdx.y * BM, n0 = blockIdx.x * BN;
    __shared__ float As[BKK][BM];   // [kk][m]
    __shared__ float Bs[BKK][BN];   // [kk][n]
    int tid = threadIdx.x;
    int tx = tid & 15, ty = tid >> 4;   // 16x16 thread grid
    float acc[8][8];
#pragma unroll
    for (int i = 0; i < 8; i++)
#pragma unroll
        for (int j = 0; j < 8; j++) acc[i][j] = 0.f;

    float pa[8], pb[8];

    // ---- preload slice 0 into registers ----
#pragma unroll
    for (int i = 0; i < 8; i++) {
        int l = tid + i * 256;
        int kk = l & 15, r = l >> 4;
        int gm = m0 + r, gk = kk;
        pa[i] = (gm < M && gk < K) ? A[(size_t)gm * K + gk] : 0.f;
    }
#pragma unroll
    for (int i = 0; i < 8; i++) {
        int l = tid + i * 256;
        int n = l & 127, kk = l >> 7;
        int gk = kk, gn = n0 + n;
        pb[i] = (gk < K && gn < N) ? B[(size_t)gk * N + gn] : 0.f;
    }

    for (int k0 = 0; k0 < K; k0 += BKK) {
        // ---- store prefetched slice to smem ----
#pragma unroll
        for (int i = 0; i < 8; i++) {
            int l = tid + i * 256;
            int kk = l & 15, r = l >> 4;
            As[kk][r] = pa[i];
        }
#pragma unroll
        for (int i = 0; i < 8; i++) {
            int l = tid + i * 256;
            int n = l & 127, kk = l >> 7;
            Bs[kk][n] = pb[i];
        }
        __syncthreads();

        // ---- issue prefetch of next slice (overlaps with compute below) ----
        int kn = k0 + BKK;
        if (kn < K) {
#pragma unroll
            for (int i = 0; i < 8; i++) {
                int l = tid + i * 256;
                int kk = l & 15, r = l >> 4;
                int gm = m0 + r, gk = kn + kk;
                pa[i] = (gm < M && gk < K) ? A[(size_t)gm * K + gk] : 0.f;
            }
#pragma unroll
            for (int i = 0; i < 8; i++) {
                int l = tid + i * 256;
                int n = l & 127, kk = l >> 7;
                int gk = kn + kk, gn = n0 + n;
                pb[i] = (gk < K && gn < N) ? B[(size_t)gk * N + gn] : 0.f;
            }
        }

        // ---- compute on current slice ----
#pragma unroll
        for (int kk = 0; kk < BKK; kk++) {
            // quadrant reads: 16B accesses at 16B stride -> conflict-free per 8-lane phase
            float4 a0 = *(const float4*)&As[kk][ty * 4];
            float4 a1 = *(const float4*)&As[kk][64 + ty * 4];
            float4 b0 = *(const float4*)&Bs[kk][tx * 4];
            float4 b1 = *(const float4*)&Bs[kk][64 + tx * 4];
            float ar[8] = {a0.x, a0.y, a0.z, a0.w, a1.x, a1.y, a1.z, a1.w};
            float br[8] = {b0.x, b0.y, b0.z, b0.w, b1.x, b1.y, b1.z, b1.w};
#pragma unroll
            for (int i = 0; i < 8; i++)
#pragma unroll
                for (int j = 0; j < 8; j++) acc[i][j] += ar[i] * br[j];
        }
        __syncthreads();
    }
#pragma unroll
    for (int i = 0; i < 8; i++) {
        int rloc = (i < 4) ? (ty * 4 + i) : (64 + ty * 4 + (i - 4));
        int gm = m0 + rloc;
        if (gm >= M) continue;
#pragma unroll
        for (int j = 0; j < 8; j++) {
            int nloc = (j < 4) ? (tx * 4 + j) : (64 + tx * 4 + (j - 4));
            int gn = n0 + nloc;
            if (gn >= N) continue;
            float vv = acc[i][j];
            if (bias) vv += bias[gn];
            C[(size_t)gm * N + gn] = vv;
        }
    }
}

// ------------------------- LSTM step -------------------------
// grid (3 utiles x 16 bgroups x 2 dirs), 128 threads; thread = unit (tid<100), 4 batches, 4 gates
__global__ void __launch_bounds__(128) lstm_step(int t) {
    int utile = blockIdx.x, bg = blockIdx.y, dir = blockIdx.z;
    int tid = threadIdx.x;
    int p = t & 1;
    __shared__ float hs[4][NH];
    int b0 = bg * 4;
    const float* hold = &g_h[((size_t)(dir * 2 + p) * NB) * NH];
    for (int i = tid; i < 4 * NH; i += 128) {
        int j = i / NH, k = i % NH;
        hs[j][k] = hold[(size_t)(b0 + j) * NH + k];
    }
    __syncthreads();
    if (tid >= 100) return;
    int u = utile * 100 + tid;
    const float* WT = dir ? g_WhhTb : g_WhhTf;
    float a0[4] = {0, 0, 0, 0}, a1[4] = {0, 0, 0, 0}, a2[4] = {0, 0, 0, 0}, a3[4] = {0, 0, 0, 0};
    for (int k = 0; k < NH; k++) {
        const float* wr = &WT[(size_t)k * NH4 + u];
        float w0 = wr[0], w1 = wr[300], w2 = wr[600], w3 = wr[900];
#pragma unroll
        for (int j = 0; j < 4; j++) {
            float h = hs[j][k];
            a0[j] += w0 * h;
            a1[j] += w1 * h;
            a2[j] += w2 * h;
            a3[j] += w3 * h;
        }
    }
    int t_eff = dir ? (NS - 1 - t) : t;
    const float* X = dir ? g_Xb : g_Xf;
#pragma unroll
    for (int j = 0; j < 4; j++) {
        int b = b0 + j;
        const float* xr = &X[((size_t)b * NS + t_eff) * NH4];
        float gi = a0[j] + xr[u];
        float gf = a1[j] + xr[300 + u];
        float gg = a2[j] + xr[600 + u];
        float go = a3[j] + xr[900 + u];
        float ii = fsigmoid_(gi), ff = fsigmoid_(gf), oo = fsigmoid_(go);
        float gt = ftanh_(gg);
        size_t cidx = ((size_t)dir * NB + b) * NH + u;
        float c = ff * g_c[cidx] + ii * gt;
        g_c[cidx] = c;
        float h = oo * ftanh_(c);
        g_h[((size_t)(dir * 2 + (1 - p)) * NB + b) * NH + u] = h;
        g_to[((size_t)b * NS + t_eff) * NH2 + dir * NH + u] = h;
    }
}

// ------------------------- adj copy (float4) -------------------------
__global__ void k_adjcopy(const float* __restrict__ adj) {
    size_t n4 = (size_t)NB * NS * NS / 4;
    const float4* src = (const float4*)adj;
    float4* dst = (float4*)g_adj;
    for (size_t i = (size_t)blockIdx.x * blockDim.x + threadIdx.x; i < n4;
         i += (size_t)gridDim.x * blockDim.x)
        dst[i] = src[i];
}

// ------------------------- relation bilinear score + scatter -------------------------
__global__ void k_score(const int* __restrict__ relv, const int* __restrict__ headv,
                        const int* __restrict__ beheadv, const float* __restrict__ bilb) {
    int warp = threadIdx.x >> 5, lane = threadIdx.x & 31;
    int idx = blockIdx.x * 8 + warp;                 // (b, r)
    if (idx >= NB * NR) return;
    int b = idx / NR, r = idx % NR;
    int rel = relv[b * NR + r];
    int hd = headv[b * NR + r];
    int bh = beheadv[b * NR + r];
    float s = 0.f;
    if (rel != 0) {
        const float* n1 = &g_to[((size_t)b * NS + hd) * NH2];
        const float* n2 = &g_to[((size_t)b * NS + bh) * NH2];
        const float* Pp = &g_P[(size_t)rel * NH4];
        for (int u = lane; u < NH2; u += 32) s += n1[u] * Pp[u] + n2[u] * Pp[NH2 + u];
    }
#pragma unroll
    for (int o = 16; o; o >>= 1) s += __shfl_xor_sync(0xffffffffu, s, o);
    if (lane == 0) {
        float sc = 1.0f / (1.0f + expf(-(s + bilb[0])));
        g_adj[((size_t)b * NS + hd) * NS + bh] = sc;
    }
}

// ------------------------- row-sum denom -------------------------
__global__ void k_denom() {
    int warp = threadIdx.x >> 5, lane = threadIdx.x & 31;
    int row = blockIdx.x * 8 + warp;                 // (b, s)
    if (row >= NB * NS) return;
    const float* ar = &g_adj[(size_t)row * NS];
    float s = 0.f;
    for (int c = lane; c < NS; c += 32) s += ar[c];
#pragma unroll
    for (int o = 16; o; o >>= 1) s += __shfl_xor_sync(0xffffffffu, s, o);
    if (lane == 0) g_denom[row] = s + 1.0f;
}

// ------------------------- position weight (float4; one block row = one (b,s)) -------------
// grid.x = NB*NS, 160 threads: NH2/4 = 150 float4 per row
__global__ void k_poswt(const float* __restrict__ in, float* __restrict__ out) {
    int bs = blockIdx.x;
    int b = bs >> 8, j = bs & 255;
    float l0 = (float)g_len[b];
    float al = (float)g_len[NB + b];
    float tl = (float)g_len[2 * NB + b];
    float l1 = l0 + al - 1.0f;
    float ctx = tl - al;
    float jj = (float)j;
    float w;
    if (jj < l0) w = 1.0f - (l0 - jj) / ctx;
    else if (jj <= l1) w = 0.0f;
    else if (jj < tl) w = 1.0f - (jj - l1) / ctx;
    else w = 0.0f;
    const float4* src = (const float4*)(in + (size_t)bs * NH2);
    float4* dst = (float4*)(out + (size_t)bs * NH2);
    int u = threadIdx.x;
    if (u < NH2 / 4) {
        float4 v = src[u];
        v.x *= w; v.y *= w; v.z *= w; v.w *= w;
        dst[u] = v;
    }
}

// ------------------------- relu(A/denom + bias) (float4; one block row = one (b,s)) --------
__global__ void k_reludb(const float* __restrict__ in, float* __restrict__ out,
                         const float* __restrict__ bias) {
    int bs = blockIdx.x;
    float inv = __frcp_rn(g_denom[bs]);
    const float4* src = (const float4*)(in + (size_t)bs * NH2);
    const float4* bi = (const float4*)bias;
    float4* dst = (float4*)(out + (size_t)bs * NH2);
    int u = threadIdx.x;
    if (u < NH2 / 4) {
        float4 v = src[u];
        float4 bb4 = bi[u];
        v.x = fmaxf(v.x * inv + bb4.x, 0.f);
        v.y = fmaxf(v.y * inv + bb4.y, 0.f);
        v.z = fmaxf(v.z * inv + bb4.z, 0.f);
        v.w = fmaxf(v.w * inv + bb4.w, 0.f);
        dst[u] = v;
    }
}

// ------------------------- masked column sum v[b] = sum_{j in [l0,l1]} X2[b,j,:] ------------
__global__ void k_vmask() {
    int b = blockIdx.x;
    int l0 = g_len[b];
    int l1 = l0 + g_len[NB + b] - 1;
    if (l1 > NS - 1) l1 = NS - 1;
    for (int u = threadIdx.x; u < NH2; u += blockDim.x) {
        float a = 0.f;
        for (int j = l0; j <= l1; j++) a += g_A[((size_t)b * NS + j) * NH2 + u];
        g_v[b * NH2 + u] = a;
    }
}

// ------------------------- attention + fc -------------------------
__global__ void __launch_bounds__(256) k_attend(const float* __restrict__ fcW,
                                                const float* __restrict__ fcb,
                                                float* __restrict__ out) {
    int b = blockIdx.x;
    __shared__ float lg[NS];
    __shared__ float red[8];
    __shared__ float ov[NH2];
    int tid = threadIdx.x, warp = tid >> 5, lane = tid & 31;
    // logits[s] = v[b] . text_out[b,s,:]
    for (int s = warp; s < NS; s += 8) {
        const float* tr = &g_to[((size_t)b * NS + s) * NH2];
        float a = 0.f;
        for (int u = lane; u < NH2; u += 32) a += g_v[b * NH2 + u] * tr[u];
#pragma unroll
        for (int o = 16; o; o >>= 1) a += __shfl_xor_sync(0xffffffffu, a, o);
        if (lane == 0) lg[s] = a;
    }
    __syncthreads();
    // softmax over 256
    float v = lg[tid];
    float m = v;
#pragma unroll
    for (int o = 16; o; o >>= 1) m = fmaxf(m, __shfl_xor_sync(0xffffffffu, m, o));
    if (lane == 0) red[warp] = m;
    __syncthreads();
    if (tid == 0) {
        float mm = red[0];
        for (int w = 1; w < 8; w++) mm = fmaxf(mm, red[w]);
        red[0] = mm;
    }
    __syncthreads();
    float mx = red[0];
    float e = expf(v - mx);
    float s = e;
#pragma unroll
    for (int o = 16; o; o >>= 1) s += __shfl_xor_sync(0xffffffffu, s, o);
    __syncthreads();
    if (lane == 0) red[warp] = s;
    __syncthreads();
    if (tid == 0) {
        float ss = 0.f;
        for (int w = 0; w < 8; w++) ss += red[w];
        red[0] = ss;
    }
    __syncthreads();
    float alpha = e / red[0];
    lg[tid] = alpha;
    __syncthreads();
    // ov[u] = sum_s alpha[s]*text_out[b,s,u]
    for (int u = tid; u < NH2; u += 256) {
        float a = 0.f;
        for (int ss = 0; ss < NS; ss++) a += lg[ss] * g_to[((size_t)b * NS + ss) * NH2 + u];
        ov[u] = a;
    }
    __syncthreads();
    if (tid < 3) {
        float a = fcb[tid];
        for (int u = 0; u < NH2; u++) a += ov[u] * fcW[u * 3 + tid];
        out[b * 3 + tid] = a;
    }
}

// ------------------------- launch -------------------------
extern "C" void kernel_launch(void* const* d_in, const int* in_sizes, int n_in,
                              void* d_out, int out_size) {
    const int* ti = (const int*)d_in[0];
    const int* ai = (const int*)d_in[1];
    const int* li = (const int*)d_in[2];
    const float* adj = (const float*)d_in[3];
    const int* headv = (const int*)d_in[4];
    const int* beheadv = (const int*)d_in[5];
    const int* relv = (const int*)d_in[6];
    const float* emb = (const float*)d_in[7];
    const float* relE = (const float*)d_in[8];
    const float* Wf_ih = (const float*)d_in[9];
    const float* Wf_hh = (const float*)d_in[10];
    const float* bf = (const float*)d_in[11];
    const float* Wb_ih = (const float*)d_in[12];
    const float* Wb_hh = (const float*)d_in[13];
    const float* bb = (const float*)d_in[14];
    const float* bilW = (const float*)d_in[15];
    const float* bilb = (const float*)d_in[16];
    const float* gc1W = (const float*)d_in[17];
    const float* gc1b = (const float*)d_in[18];
    const float* gc2W = (const float*)d_in[19];
    const float* gc2b = (const float*)d_in[20];
    const float* fcW = (const float*)d_in[21];
    const float* fcb = (const float*)d_in[22];
    float* out = (float*)d_out;

    k_lens<<<1, 64>>>(ti, ai, li);

    {
        size_t n = (size_t)NB * NS * (NE / 4);
        k_embed<<<(int)((n + 255) / 256), 256>>>(ti, emb);
    }

    int tblk = (NH4 * NE + 255) / 256;
    float* WihTf; cudaGetSymbolAddress((void**)&WihTf, g_WihTf);
    float* WihTb; cudaGetSymbolAddress((void**)&WihTb, g_WihTb);
    float* WhhTf; cudaGetSymbolAddress((void**)&WhhTf, g_WhhTf);
    float* WhhTb; cudaGetSymbolAddress((void**)&WhhTb, g_WhhTb);
    float* textp; cudaGetSymbolAddress((void**)&textp, g_text);
    float* Xfp;   cudaGetSymbolAddress((void**)&Xfp, g_Xf);
    float* Xbp;   cudaGetSymbolAddress((void**)&Xbp, g_Xb);
    float* top;   cudaGetSymbolAddress((void**)&top, g_to);
    float* adjp;  cudaGetSymbolAddress((void**)&adjp, g_adj);
    float* pwp;   cudaGetSymbolAddress((void**)&pwp, g_pw);
    float* Hp;    cudaGetSymbolAddress((void**)&Hp, g_H);
    float* Ap;    cudaGetSymbolAddress((void**)&Ap, g_A);
    float* X1p;   cudaGetSymbolAddress((void**)&X1p, g_X1);

    k_transpose<<<tblk, 256>>>(Wf_ih, WihTf, NH4, NE);
    k_transpose<<<tblk, 256>>>(Wb_ih, WihTb, NH4, NE);
    k_transpose<<<tblk, 256>>>(Wf_hh, WhhTf, NH4, NH);
    k_transpose<<<tblk, 256>>>(Wb_hh, WhhTb, NH4, NH);

    k_pcomp<<<NRELN, 256>>>(bilW, relE);

    // input projections (+bias)
    {
        dim3 g((NH4 + BN - 1) / BN, (NB * NS + BM - 1) / BM, 1);
        gemm_nn<<<g, 256>>>(textp, WihTf, Xfp, bf, NB * NS, NH4, NE, 0, 0, 0);
        gemm_nn<<<g, 256>>>(textp, WihTb, Xbp, bb, NB * NS, NH4, NE, 0, 0, 0);
    }

    k_zero_state<<<256, 256>>>();
    for (int t = 0; t < NS; t++) lstm_step<<<dim3(3, 16, 2), 128>>>(t);

    k_adjcopy<<<1024, 256>>>(adj);
    k_score<<<(NB * NR + 7) / 8, 256>>>(relv, headv, beheadv, bilb);
    k_denom<<<(NB * NS + 7) / 8, 256>>>();

    // GCN layer 1
    k_poswt<<<NB * NS, 160>>>(top, pwp);
    {
        dim3 g((NH2 + BN - 1) / BN, (NB * NS + BM - 1) / BM, 1);
        gemm_nn<<<g, 256>>>(pwp, gc1W, Hp, nullptr, NB * NS, NH2, NH2, 0, 0, 0);
    }
    {
        dim3 g((NH2 + BN - 1) / BN, (NS + BM - 1) / BM, NB);
        gemm_nn<<<g, 256>>>(adjp, Hp, Ap, nullptr, NS, NH2, NS,
                            (long)NS * NS, (long)NS * NH2, (long)NS * NH2);
    }
    k_reludb<<<NB * NS, 160>>>(Ap, X1p, gc1b);

    // GCN layer 2
    k_poswt<<<NB * NS, 160>>>(X1p, pwp);
    {
        dim3 g((NH2 + BN - 1) / BN, (NB * NS + BM - 1) / BM, 1);
        gemm_nn<<<g, 256>>>(pwp, gc2W, Hp, nullptr, NB * NS, NH2, NH2, 0, 0, 0);
    }
    {
        dim3 g((NH2 + BN - 1) / BN, (NS + BM - 1) / BM, NB);
        gemm_nn<<<g, 256>>>(adjp, Hp, Ap, nullptr, NS, NH2, NS,
                            (long)NS * NS, (long)NS * NH2, (long)NS * NH2);
    }
    k_reludb<<<NB * NS, 160>>>(Ap, Ap, gc2b);

    // mask-sum, attention, fc
    k_vmask<<<NB, 256>>>();
    k_attend<<<NB, 256>>>(fcW, fcb, out);
}